// round 6
// baseline (speedup 1.0000x reference)
#include <cuda_runtime.h>
#include <cstdint>

#define BB   8
#define CC   64
#define NP   12800
#define NS   3200
#define KNN  16
#define HWD  19200
#define NOUT 22400   // HWD + NS

#define RS    132                 // smem row stride (floats), 16B-aligned, padded
#define SMEMB (2 * 64 * RS * 4)   // Wd + Xs = 67584 bytes

// ---------------- scratch (device globals; no allocation) ----------------
__device__ __align__(16) float g_pT   [(size_t)BB * NP * CC];   // p transposed  [B, NP, 64]
__device__ __align__(16) float g_rgbT [(size_t)BB * HWD * CC];  // rgb transposed [B, HW, 64]
__device__ __align__(16) float g_pembT[(size_t)BB * NS * CC];   // p_emb0        [B, NS, 64]
__device__ __align__(16) float g_r2pgT[(size_t)BB * NS * CC];   // rgb gather+max
__device__ __align__(16) float g_qT   [(size_t)BB * NS * CC];   // Wfuse_hi @ p2r
__device__ __align__(16) float g_r2ppT[(size_t)BB * NS * CC];   // r2p_pre

// ---------------- packed fp32x2 helpers ----------------
__device__ __forceinline__ unsigned long long ffma2(unsigned long long a,
                                                    unsigned long long b,
                                                    unsigned long long c) {
    unsigned long long d;
    asm("fma.rn.f32x2 %0, %1, %2, %3;" : "=l"(d) : "l"(a), "l"(b), "l"(c));
    return d;
}
__device__ __forceinline__ float2 u2f(unsigned long long u) {
    float2 f;
    asm("mov.b64 {%0, %1}, %2;" : "=f"(f.x), "=f"(f.y) : "l"(u));
    return f;
}

// ---------------- transpose [B,64,N] -> [B,N,64] ----------------
__device__ __forceinline__ void transpose_body(const float* __restrict__ src,
                                               float* __restrict__ dst, int N, int n0) {
    __shared__ __align__(16) float s[32][33];
    const int b  = blockIdx.z;
    const int c0 = blockIdx.y * 32;
    const int tx = threadIdx.x, ty = threadIdx.y;
    const float* sp = src + ((size_t)b * CC + c0) * N + n0;
#pragma unroll
    for (int i = 0; i < 4; i++)
        s[ty + 8 * i][tx] = sp[(size_t)(ty + 8 * i) * N + tx];
    __syncthreads();
    float* dp = dst + ((size_t)b * N + n0) * CC + c0;
#pragma unroll
    for (int i = 0; i < 4; i++)
        dp[(size_t)(ty + 8 * i) * CC + tx] = s[tx][ty + 8 * i];
}

__global__ void __launch_bounds__(256, 2)
k_transpose_all(const float* __restrict__ p, const float* __restrict__ rgb) {
    if (blockIdx.x < NP / 32) transpose_body(p,   g_pT,   NP,  blockIdx.x * 32);
    else                      transpose_body(rgb, g_rgbT, HWD, (blockIdx.x - NP / 32) * 32);
}

// ---------------- gather + maxpool: one warp per (b,m) ----------------
__device__ __forceinline__ void gather_body(const float* __restrict__ srcT,
                                            const int* __restrict__ idx,
                                            float* __restrict__ dstT, int Nsrc, int bx) {
    const int wid  = threadIdx.x >> 5;
    const int lane = threadIdx.x & 31;
    const int gid  = bx * 8 + wid;            // == b*NS + m
    const int b    = gid / NS;
    const int* ip = idx + (size_t)gid * KNN;
    int id[KNN];
#pragma unroll
    for (int k = 0; k < KNN; k++) id[k] = __ldg(ip + k);
    float2 v[KNN];
#pragma unroll
    for (int k = 0; k < KNN; k++) {
        const float2* r = (const float2*)(srcT + ((size_t)b * Nsrc + id[k]) * CC);
        v[k] = __ldg(r + lane);
    }
    float2 acc = v[0];
#pragma unroll
    for (int k = 1; k < KNN; k++) {
        acc.x = fmaxf(acc.x, v[k].x);
        acc.y = fmaxf(acc.y, v[k].y);
    }
    ((float2*)(dstT + (size_t)gid * CC))[lane] = acc;
}

__global__ void __launch_bounds__(256, 2)
k_gather_all(const int* __restrict__ pool_idx, const int* __restrict__ r2p_idx) {
    const int half = BB * NS / 8;  // 3200
    if (blockIdx.x < half) gather_body(g_pT,   pool_idx, g_pembT, NP,  blockIdx.x);
    else                   gather_body(g_rgbT, r2p_idx,  g_r2pgT, HWD, blockIdx.x - half);
}

// ---------------- GEMM tile loaders (Wd dup-packed, Xs [c][n] 64x128) ----------------
// Wd[c][2o], Wd[c][2o+1] = w[o][c]  (pairs so LDS.128 yields packed broadcasts)
__device__ __forceinline__ void load_wd(float* Wd, const float* __restrict__ w,
                                        int stride, int t) {
#pragma unroll
    for (int i = 0; i < 16; i++) {
        int f = t + 256 * i;                    // f < 4096
        int o = f >> 6, c = f & 63;
        float v = __ldg(w + (size_t)o * stride + c);
        Wd[c * RS + 2 * o]     = v;
        Wd[c * RS + 2 * o + 1] = v;
    }
}
// X from point-major [n][c] source (128 rows x 64 c)
__device__ __forceinline__ void load_x_pm(float* Xs, const float* __restrict__ x, int t) {
#pragma unroll
    for (int i = 0; i < 32; i++) {
        int f = t + 256 * i;                    // f < 8192
        int c = f & 63, n = f >> 6;
        Xs[c * RS + n] = x[(size_t)n * CC + c];
    }
}
// X from channel-major source (row stride Nsrc), fully coalesced + conflict-free
__device__ __forceinline__ void load_x_cm(float* Xs, const float* __restrict__ x,
                                          int Nsrc, int t) {
#pragma unroll
    for (int i = 0; i < 8; i++) {
        int f4 = t + 256 * i;                   // f4 < 2048
        int n4 = f4 & 31, c = f4 >> 5;
        float4 v = *(const float4*)(x + (size_t)c * Nsrc + 4 * n4);
        *(float4*)(Xs + c * RS + 4 * n4) = v;
    }
}

// ---------------- FFMA2 GEMM core: 64 K-steps, thread tile 4o x 8n ----------------
// o in {2ty, 2ty+1, 2ty+32, 2ty+33}; n in {4tx..4tx+3, 4tx+64..4tx+67}
__device__ __forceinline__ void mm64(const float* Wd, const float* Xs, int tx, int ty,
                                     unsigned long long acc[4][4]) {
#pragma unroll 8
    for (int c = 0; c < 64; c++) {
        const float* wr = Wd + c * RS;
        const float* xr = Xs + c * RS;
        ulonglong2 wa = *(const ulonglong2*)(wr + 4 * ty);
        ulonglong2 wb = *(const ulonglong2*)(wr + 4 * ty + 64);
        ulonglong2 xa = *(const ulonglong2*)(xr + 4 * tx);
        ulonglong2 xb = *(const ulonglong2*)(xr + 4 * tx + 64);
        unsigned long long w[4]  = {wa.x, wa.y, wb.x, wb.y};
        unsigned long long xx[4] = {xa.x, xa.y, xb.x, xb.y};
#pragma unroll
        for (int i = 0; i < 4; i++)
#pragma unroll
            for (int p = 0; p < 4; p++)
                acc[i][p] = ffma2(w[i], xx[p], acc[i][p]);
    }
}

// ---------------- pre kernel: z=0 p2r chain (-> g_qT), z=1 r2p_pre (-> g_r2ppT) -------
__global__ void __launch_bounds__(256, 2)
k_pre(const float* __restrict__ w_p2r_pre, const float* __restrict__ s_p2r_pre,
      const float* __restrict__ b_p2r_pre, const float* __restrict__ w_p2r_fuse,
      const float* __restrict__ w_r2p_pre, const float* __restrict__ s_r2p_pre,
      const float* __restrict__ b_r2p_pre) {
    extern __shared__ float sm[];
    float* Wd = sm;
    float* Xs = sm + 64 * RS;
    const int b = blockIdx.y, n0 = blockIdx.x * 128;
    const int t = threadIdx.x, tx = t & 15, ty = t >> 4;
    const int o_[4] = {2 * ty, 2 * ty + 1, 2 * ty + 32, 2 * ty + 33};

    if (blockIdx.z == 0) {
        load_x_pm(Xs, g_pembT + ((size_t)b * NS + n0) * CC, t);
        load_wd(Wd, w_p2r_pre, 64, t);
        __syncthreads();
        unsigned long long acc[4][4] = {};
        mm64(Wd, Xs, tx, ty, acc);

        float s4[4], b4[4];
#pragma unroll
        for (int i = 0; i < 4; i++) { s4[i] = __ldg(s_p2r_pre + o_[i]); b4[i] = __ldg(b_p2r_pre + o_[i]); }
        __syncthreads();            // everyone done reading Xs/Wd
#pragma unroll
        for (int p = 0; p < 4; p++) {
            int nb = 4 * tx + 2 * (p & 1) + 64 * (p >> 1);
#pragma unroll
            for (int i = 0; i < 4; i++) {
                float2 v = u2f(acc[i][p]);
                v.x = fmaxf(v.x * s4[i] + b4[i], 0.0f);
                v.y = fmaxf(v.y * s4[i] + b4[i], 0.0f);
                *(float2*)(Xs + o_[i] * RS + nb) = v;
            }
        }
        load_wd(Wd, w_p2r_fuse + 64, 128, t);    // point half of fuse weights
        __syncthreads();

        unsigned long long acc2[4][4] = {};
        mm64(Wd, Xs, tx, ty, acc2);

        float* qp = g_qT + ((size_t)b * NS + n0) * CC;
#pragma unroll
        for (int p = 0; p < 4; p++) {
            int nb = 4 * tx + 2 * (p & 1) + 64 * (p >> 1);
            float2 a0 = u2f(acc2[0][p]), a1 = u2f(acc2[1][p]);
            float2 a2 = u2f(acc2[2][p]), a3 = u2f(acc2[3][p]);
            *(float2*)(qp + (size_t)nb * CC + 2 * ty)            = make_float2(a0.x, a1.x);
            *(float2*)(qp + (size_t)nb * CC + 2 * ty + 32)       = make_float2(a2.x, a3.x);
            *(float2*)(qp + (size_t)(nb + 1) * CC + 2 * ty)      = make_float2(a0.y, a1.y);
            *(float2*)(qp + (size_t)(nb + 1) * CC + 2 * ty + 32) = make_float2(a2.y, a3.y);
        }
    } else {
        load_x_pm(Xs, g_r2pgT + ((size_t)b * NS + n0) * CC, t);
        load_wd(Wd, w_r2p_pre, 64, t);
        __syncthreads();
        unsigned long long acc[4][4] = {};
        mm64(Wd, Xs, tx, ty, acc);

        float s4[4], b4[4];
#pragma unroll
        for (int i = 0; i < 4; i++) { s4[i] = __ldg(s_r2p_pre + o_[i]); b4[i] = __ldg(b_r2p_pre + o_[i]); }
        float* op = g_r2ppT + ((size_t)b * NS + n0) * CC;
#pragma unroll
        for (int p = 0; p < 4; p++) {
            int nb = 4 * tx + 2 * (p & 1) + 64 * (p >> 1);
            float2 a[4];
#pragma unroll
            for (int i = 0; i < 4; i++) {
                a[i] = u2f(acc[i][p]);
                a[i].x = fmaxf(a[i].x * s4[i] + b4[i], 0.0f);
                a[i].y = fmaxf(a[i].y * s4[i] + b4[i], 0.0f);
            }
            *(float2*)(op + (size_t)nb * CC + 2 * ty)            = make_float2(a[0].x, a[1].x);
            *(float2*)(op + (size_t)nb * CC + 2 * ty + 32)       = make_float2(a[2].x, a[3].x);
            *(float2*)(op + (size_t)(nb + 1) * CC + 2 * ty)      = make_float2(a[0].y, a[1].y);
            *(float2*)(op + (size_t)(nb + 1) * CC + 2 * ty + 32) = make_float2(a[2].y, a[3].y);
        }
    }
}

// ---------------- rgb_out = relu(s*(W_lo@rgb + q[:, p2r_idx]) + b) ----------------
__global__ void __launch_bounds__(256, 2)
k_rgb_out(const float* __restrict__ rgb, const float* __restrict__ w_fuse,
          const float* __restrict__ s, const float* __restrict__ bias,
          const int* __restrict__ p2r_idx, float* __restrict__ out) {
    extern __shared__ float sm[];
    float* Wd = sm;
    float* Xs = sm + 64 * RS;
    const int b = blockIdx.y, n0 = blockIdx.x * 128;
    const int t = threadIdx.x, tx = t & 15, ty = t >> 4;
    const int o_[4] = {2 * ty, 2 * ty + 1, 2 * ty + 32, 2 * ty + 33};

    load_x_cm(Xs, rgb + (size_t)b * CC * HWD + n0, HWD, t);
    load_wd(Wd, w_fuse, 128, t);
    __syncthreads();
    unsigned long long acc[4][4] = {};
    mm64(Wd, Xs, tx, ty, acc);

    float s4[4], b4[4];
#pragma unroll
    for (int i = 0; i < 4; i++) { s4[i] = __ldg(s + o_[i]); b4[i] = __ldg(bias + o_[i]); }

    const int* ip = p2r_idx + (size_t)b * HWD + n0;
    const float* qbase = g_qT + (size_t)b * NS * CC;

#pragma unroll
    for (int half = 0; half < 2; half++) {          // p = 2*half, 2*half+1 -> one float4/o
        float2 va[4], vb[4];
#pragma unroll
        for (int pp = 0; pp < 2; pp++) {
            int p  = 2 * half + pp;
            int nb = 4 * tx + 2 * pp + 64 * half;
            int ia = __ldg(ip + nb), ib = __ldg(ip + nb + 1);
            const float* qa = qbase + (size_t)ia * CC;
            const float* qc = qbase + (size_t)ib * CC;
            float2 qa01 = *(const float2*)(qa + 2 * ty);
            float2 qa23 = *(const float2*)(qa + 2 * ty + 32);
            float2 qc01 = *(const float2*)(qc + 2 * ty);
            float2 qc23 = *(const float2*)(qc + 2 * ty + 32);
            float qav[4] = {qa01.x, qa01.y, qa23.x, qa23.y};
            float qcv[4] = {qc01.x, qc01.y, qc23.x, qc23.y};
#pragma unroll
            for (int i = 0; i < 4; i++) {
                float2 v = u2f(acc[i][p]);
                v.x = fmaxf((v.x + qav[i]) * s4[i] + b4[i], 0.0f);
                v.y = fmaxf((v.y + qcv[i]) * s4[i] + b4[i], 0.0f);
                if (pp == 0) va[i] = v; else vb[i] = v;
            }
        }
#pragma unroll
        for (int i = 0; i < 4; i++) {
            float4 v4 = make_float4(va[i].x, va[i].y, vb[i].x, vb[i].y);
            *(float4*)(out + ((size_t)(b * CC + o_[i])) * NOUT + n0 + 4 * tx + 64 * half) = v4;
        }
    }
}

// ---------------- p_out = relu(s*(Wf_lo@p_emb0 + Wf_hi@r2p_pre) + b) ----------------
__global__ void __launch_bounds__(256, 2)
k_p_out(const float* __restrict__ w_fuse, const float* __restrict__ s,
        const float* __restrict__ bias, float* __restrict__ out) {
    extern __shared__ float sm[];
    float* Wd = sm;
    float* Xs = sm + 64 * RS;
    const int b = blockIdx.y, n0 = blockIdx.x * 128;
    const int t = threadIdx.x, tx = t & 15, ty = t >> 4;
    const int o_[4] = {2 * ty, 2 * ty + 1, 2 * ty + 32, 2 * ty + 33};

    unsigned long long acc[4][4] = {};

    load_x_pm(Xs, g_pembT + ((size_t)b * NS + n0) * CC, t);
    load_wd(Wd, w_fuse, 128, t);
    __syncthreads();
    mm64(Wd, Xs, tx, ty, acc);
    __syncthreads();

    load_x_pm(Xs, g_r2ppT + ((size_t)b * NS + n0) * CC, t);
    load_wd(Wd, w_fuse + 64, 128, t);
    __syncthreads();
    mm64(Wd, Xs, tx, ty, acc);

    float s4[4], b4[4];
#pragma unroll
    for (int i = 0; i < 4; i++) { s4[i] = __ldg(s + o_[i]); b4[i] = __ldg(bias + o_[i]); }

#pragma unroll
    for (int half = 0; half < 2; half++) {
#pragma unroll
        for (int i = 0; i < 4; i++) {
            float2 a0 = u2f(acc[i][2 * half]);
            float2 a1 = u2f(acc[i][2 * half + 1]);
            float4 v4 = make_float4(fmaxf(a0.x * s4[i] + b4[i], 0.0f),
                                    fmaxf(a0.y * s4[i] + b4[i], 0.0f),
                                    fmaxf(a1.x * s4[i] + b4[i], 0.0f),
                                    fmaxf(a1.y * s4[i] + b4[i], 0.0f));
            *(float4*)(out + ((size_t)(b * CC + o_[i])) * NOUT + HWD + n0 + 4 * tx + 64 * half) = v4;
        }
    }
}

// ---------------- launch ----------------
extern "C" void kernel_launch(void* const* d_in, const int* in_sizes, int n_in,
                              void* d_out, int out_size) {
    const float* rgb_feat   = (const float*)d_in[0];
    const float* p_feat     = (const float*)d_in[1];
    const float* w_p2r_pre  = (const float*)d_in[2];
    const float* s_p2r_pre  = (const float*)d_in[3];
    const float* b_p2r_pre  = (const float*)d_in[4];
    const float* w_p2r_fuse = (const float*)d_in[5];
    const float* s_p2r_fuse = (const float*)d_in[6];
    const float* b_p2r_fuse = (const float*)d_in[7];
    const float* w_r2p_pre  = (const float*)d_in[8];
    const float* s_r2p_pre  = (const float*)d_in[9];
    const float* b_r2p_pre  = (const float*)d_in[10];
    const float* w_r2p_fuse = (const float*)d_in[11];
    const float* s_r2p_fuse = (const float*)d_in[12];
    const float* b_r2p_fuse = (const float*)d_in[13];
    const int*   pool_idx   = (const int*)d_in[14];
    const int*   p2r_idx    = (const int*)d_in[15];
    const int*   r2p_idx    = (const int*)d_in[16];
    float* out = (float*)d_out;

    cudaFuncSetAttribute(k_pre,     cudaFuncAttributeMaxDynamicSharedMemorySize, SMEMB);
    cudaFuncSetAttribute(k_rgb_out, cudaFuncAttributeMaxDynamicSharedMemorySize, SMEMB);
    cudaFuncSetAttribute(k_p_out,   cudaFuncAttributeMaxDynamicSharedMemorySize, SMEMB);

    k_transpose_all<<<dim3(NP / 32 + HWD / 32, 2, BB), dim3(32, 8)>>>(p_feat, rgb_feat);
    k_gather_all<<<2 * BB * NS / 8, 256>>>(pool_idx, r2p_idx);

    k_pre<<<dim3(NS / 128, BB, 2), 256, SMEMB>>>(w_p2r_pre, s_p2r_pre, b_p2r_pre, w_p2r_fuse,
                                                 w_r2p_pre, s_r2p_pre, b_r2p_pre);

    k_rgb_out<<<dim3(HWD / 128, BB), 256, SMEMB>>>(rgb_feat, w_p2r_fuse, s_p2r_fuse,
                                                   b_p2r_fuse, p2r_idx, out);
    k_p_out<<<dim3(NS / 128, BB), 256, SMEMB>>>(w_r2p_fuse, s_r2p_fuse, b_r2p_fuse, out);
}